// round 12
// baseline (speedup 1.0000x reference)
#include <cuda_runtime.h>

// Problem constants
#define BSZ     256
#define IDIM    182
#define IHALF   91           // dual-stream reduction: i and i+91
#define TSTEPS  2000
#define H0LEN   1024         // half 0: t in [0,1024)    -- 128B-aligned rows
#define H1LEN   976          // half 1: t in [1024,2000) -- base offset 4096B, aligned
#define OCH     2
#define CHUNK   4            // steps per thread in scan phase
#define GRID    (BSZ * 2)    // CTA 2b+h: batch b, t-half h

// boundary handoff: half-0 final state (syn0,mem0,syn1,mem1) + flag per batch
__device__ float g_state[BSZ][4];
__device__ volatile unsigned g_flag[BSZ];   // zero-init; consumer resets -> replay-safe

// ---------------------------------------------------------------------------
// Fully fused, zero-scratch kernel; line-aligned halves; dual-stream GEMM.
//  - i=0 input loads are prefetched BEFORE the W smem load + barrier, so the
//    DRAM stream starts immediately at kernel launch (all 512 CTAs are one
//    wave; without this the whole chip idles during the W load).
//  - Half 0 publishes its boundary state right after the warp-total
//    composition (state is final there), overlapping half 1's scan with
//    half 0's output replay on the tail critical path.
//  Spin safety: __launch_bounds__(256,4) -> all 512 CTAs co-resident
//  (148*4 = 592 >= 512); producer never blocks.
// ---------------------------------------------------------------------------
__global__ __launch_bounds__(256, 4)
void snn_fused_kernel(const float* __restrict__ inp,   // [B, I, T]
                      const float* __restrict__ W,     // [O, I]
                      const float* __restrict__ bias,  // [O]
                      const float* __restrict__ alpha,
                      const float* __restrict__ beta,
                      float* __restrict__ out)         // [B, T, O]
{
    __shared__ float  Wsh[OCH][IDIM];
    __shared__ float4 csh[OCH][256];    // slot j = currents for local t [4j,4j+4)
    __shared__ float  Ts[OCH][8][2];    // warp totals (syn, mem)
    __shared__ float  Es[OCH][8][2];    // warp exclusive prefixes
    __shared__ float  Bnd[4];           // boundary seed

    const int tid = threadIdx.x;
    const int b   = blockIdx.x >> 1;
    const int h   = blockIdx.x & 1;

    const int tbase = h ? H0LEN : 0;                   // this half's first t
    const int nch   = h ? (H1LEN / 4) : (H0LEN / 4);   // 244 or 256 live chunks
    const bool gl   = (tid < nch);

    // ---- prefetch i=0 input loads BEFORE the W barrier (hide start bubble) ----
    const int t0 = tbase + tid * 4;
    const float* ib_lo = inp + (size_t)b * IDIM * TSTEPS + t0;
    const float* ib_hi = ib_lo + (size_t)IHALF * TSTEPS;
    float4 pl, ph;
    if (gl) {
        pl = __ldcs(reinterpret_cast<const float4*>(ib_lo));
        ph = __ldcs(reinterpret_cast<const float4*>(ib_hi));
    }

    for (int k = tid; k < OCH * IDIM; k += 256)
        Wsh[k / IDIM][k % IDIM] = W[k];
    __syncthreads();

    // ======================= phase 1: GEMM into SMEM ==========================
    if (gl) {
        float4 acc0, acc1;
        {   // peeled i = 0
            const float wl0 = Wsh[0][0], wl1 = Wsh[1][0];
            const float wh0 = Wsh[0][IHALF], wh1 = Wsh[1][IHALF];
            acc0.x = fmaf(wh0, ph.x, wl0 * pl.x); acc0.y = fmaf(wh0, ph.y, wl0 * pl.y);
            acc0.z = fmaf(wh0, ph.z, wl0 * pl.z); acc0.w = fmaf(wh0, ph.w, wl0 * pl.w);
            acc1.x = fmaf(wh1, ph.x, wl1 * pl.x); acc1.y = fmaf(wh1, ph.y, wl1 * pl.y);
            acc1.z = fmaf(wh1, ph.z, wl1 * pl.z); acc1.w = fmaf(wh1, ph.w, wl1 * pl.w);
        }

        #pragma unroll 6
        for (int i = 1; i < IHALF; i++) {   // 90 iterations = 6 * 15
            const float4 xl = __ldcs(reinterpret_cast<const float4*>(ib_lo + (size_t)i * TSTEPS));
            const float4 xh = __ldcs(reinterpret_cast<const float4*>(ib_hi + (size_t)i * TSTEPS));
            const float wl0 = Wsh[0][i];
            const float wl1 = Wsh[1][i];
            const float wh0 = Wsh[0][i + IHALF];
            const float wh1 = Wsh[1][i + IHALF];
            acc0.x = fmaf(wl0, xl.x, acc0.x); acc0.y = fmaf(wl0, xl.y, acc0.y);
            acc0.z = fmaf(wl0, xl.z, acc0.z); acc0.w = fmaf(wl0, xl.w, acc0.w);
            acc1.x = fmaf(wl1, xl.x, acc1.x); acc1.y = fmaf(wl1, xl.y, acc1.y);
            acc1.z = fmaf(wl1, xl.z, acc1.z); acc1.w = fmaf(wl1, xl.w, acc1.w);
            acc0.x = fmaf(wh0, xh.x, acc0.x); acc0.y = fmaf(wh0, xh.y, acc0.y);
            acc0.z = fmaf(wh0, xh.z, acc0.z); acc0.w = fmaf(wh0, xh.w, acc0.w);
            acc1.x = fmaf(wh1, xh.x, acc1.x); acc1.y = fmaf(wh1, xh.y, acc1.y);
            acc1.z = fmaf(wh1, xh.z, acc1.z); acc1.w = fmaf(wh1, xh.w, acc1.w);
        }

        const float b0 = bias[0];
        const float b1 = bias[1];
        acc0.x += b0; acc0.y += b0; acc0.z += b0; acc0.w += b0;
        acc1.x += b1; acc1.y += b1; acc1.z += b1; acc1.w += b1;

        csh[0][tid] = acc0;
        csh[1][tid] = acc1;
    } else {
        const float4 z = make_float4(0.f, 0.f, 0.f, 0.f);
        csh[0][tid] = z;
        csh[1][tid] = z;
    }
    __syncthreads();

    // ======================= phase 2: scan of this half ======================
    const int j    = tid;               // chunk index 0..255
    const int lane = j & 31;
    const int w    = j >> 5;
    const bool live = gl;

    float a[OCH], m[OCH];
    a[0] = __saturatef(alpha[0]); a[1] = __saturatef(alpha[1]);
    m[0] = __saturatef(beta[0]);  m[1] = __saturatef(beta[1]);

    // phase A: chunk currents from SMEM, local scan from zero state
    float c[OCH][CHUNK];
    float vs[OCH], vm[OCH];
    #pragma unroll
    for (int o = 0; o < OCH; o++) {
        const float4 x = csh[o][j];
        c[o][0] = x.x; c[o][1] = x.y; c[o][2] = x.z; c[o][3] = x.w;
        float s = 0.f, q = 0.f;
        #pragma unroll
        for (int k = 0; k < CHUNK; k++) {
            s = fmaf(a[o], s, c[o][k]);
            q = fmaf(m[o], q, s);
        }
        vs[o] = s; vm[o] = q;
    }

    // P = M^CHUNK per channel:  M = [[a,0],[a,m]], M^k = [[A,0],[C,B]]
    float PA[OCH], PB[OCH], PC[OCH];
    #pragma unroll
    for (int o = 0; o < OCH; o++) {
        float A = 1.f, B = 1.f, C = 0.f;
        #pragma unroll
        for (int k = 0; k < CHUNK; k++) {
            A = a[o] * A;
            C = fmaf(m[o], C, A);
            B = m[o] * B;
        }
        PA[o] = A; PB[o] = B; PC[o] = C;
    }

    // phase B: Kogge-Stone intra-warp scan; build L = P^lane on the fly
    float LA[OCH] = {1.f, 1.f}, LB[OCH] = {1.f, 1.f}, LC[OCH] = {0.f, 0.f};

    #pragma unroll
    for (int d = 1; d <= 16; d <<= 1) {
        #pragma unroll
        for (int o = 0; o < OCH; o++) {
            if (lane & d) {
                const float nA = LA[o] * PA[o];
                const float nB = LB[o] * PB[o];
                const float nC = fmaf(LC[o], PA[o], LB[o] * PC[o]);
                LA[o] = nA; LB[o] = nB; LC[o] = nC;
            }
        }
        #pragma unroll
        for (int o = 0; o < OCH; o++) {
            const float ws = __shfl_up_sync(0xffffffffu, vs[o], d);
            const float wq = __shfl_up_sync(0xffffffffu, vm[o], d);
            if (lane >= d) {
                vm[o] = fmaf(PC[o], ws, fmaf(PB[o], wq, vm[o]));
                vs[o] = fmaf(PA[o], ws, vs[o]);
            }
        }
        #pragma unroll
        for (int o = 0; o < OCH; o++) {
            PC[o] = PC[o] * (PA[o] + PB[o]);
            PA[o] = PA[o] * PA[o];
            PB[o] = PB[o] * PB[o];
        }
    }
    // P now holds P^32 (warp-span matrix)

    if (lane == 31) {
        #pragma unroll
        for (int o = 0; o < OCH; o++) {
            Ts[o][w][0] = vs[o];
            Ts[o][w][1] = vm[o];
        }
    }

    // boundary seed: half 0 -> zeros; half 1 -> wait for half 0's final state
    if (tid == 0) {
        if (h == 1) {
            while (g_flag[b] == 0u) { /* brief spin; producer co-resident */ }
            __threadfence();            // acquire: order state reads after flag
            Bnd[0] = g_state[b][0];
            Bnd[1] = g_state[b][1];
            Bnd[2] = g_state[b][2];
            Bnd[3] = g_state[b][3];
            g_flag[b] = 0u;             // consume: reset for next graph replay
        } else {
            Bnd[0] = 0.f; Bnd[1] = 0.f; Bnd[2] = 0.f; Bnd[3] = 0.f;
        }
    }
    __syncthreads();

    // serial composition over 8 warp totals, seeded with boundary state.
    // For h=0 the final (Ss,Sm) IS the boundary state after t=1023: publish it
    // here (before phase C) so half 1 can proceed while we replay/store.
    if (j < OCH) {
        const int o = j;
        float Ss = Bnd[2 * o + 0];
        float Sm = Bnd[2 * o + 1];
        #pragma unroll
        for (int k = 0; k < 8; k++) {
            Es[o][k][0] = Ss;
            Es[o][k][1] = Sm;
            const float ts = Ts[o][k][0];
            const float tm = Ts[o][k][1];
            const float ns = fmaf(PA[o], Ss, ts);
            const float nm = fmaf(PC[o], Ss, fmaf(PB[o], Sm, tm));
            Ss = ns; Sm = nm;
        }
        if (h == 0) {
            g_state[b][2 * o + 0] = Ss;
            g_state[b][2 * o + 1] = Sm;
            __threadfence();            // release this channel's state pair
        }
    }
    __syncthreads();                    // Es visible; both state pairs fenced
    if (h == 0 && tid == 0) {
        __threadfence();
        g_flag[b] = 1u;                 // release flag after both pairs
    }

    // phase C: chunk prefix = P^lane * E_w + intra-warp exclusive; replay & store
    if (live) {
        float pre_s[OCH], pre_m[OCH];
        #pragma unroll
        for (int o = 0; o < OCH; o++) {
            float Xs = __shfl_up_sync(0xffffffffu, vs[o], 1);
            float Xm = __shfl_up_sync(0xffffffffu, vm[o], 1);
            if (lane == 0) { Xs = 0.f; Xm = 0.f; }
            const float es = Es[o][w][0];
            const float em = Es[o][w][1];
            pre_s[o] = fmaf(LA[o], es, Xs);
            pre_m[o] = fmaf(LC[o], es, fmaf(LB[o], em, Xm));
        }
        float s0 = pre_s[0], q0 = pre_m[0];
        float s1 = pre_s[1], q1 = pre_m[1];

        float r[2 * CHUNK];
        #pragma unroll
        for (int k = 0; k < CHUNK; k++) {
            s0 = fmaf(a[0], s0, c[0][k]); q0 = fmaf(m[0], q0, s0);
            s1 = fmaf(a[1], s1, c[1][k]); q1 = fmaf(m[1], q1, s1);
            r[2 * k + 0] = q0;
            r[2 * k + 1] = q1;
        }

        // out[b][t][o], t = tbase + j*4 : 8 floats = two float4 streaming stores
        float4* ob = reinterpret_cast<float4*>(out + ((size_t)b * TSTEPS + tbase + j * 4) * OCH);
        __stcs(ob + 0, make_float4(r[0], r[1], r[2], r[3]));
        __stcs(ob + 1, make_float4(r[4], r[5], r[6], r[7]));
    }
}

extern "C" void kernel_launch(void* const* d_in, const int* in_sizes, int n_in,
                              void* d_out, int out_size)
{
    const float* inp   = (const float*)d_in[0]; // [256,182,2000]
    const float* W     = (const float*)d_in[1]; // [2,182]
    const float* bias  = (const float*)d_in[2]; // [2]
    const float* alpha = (const float*)d_in[3]; // [2]
    const float* beta  = (const float*)d_in[4]; // [2]
    float* out = (float*)d_out;                 // [256,2000,2]

    snn_fused_kernel<<<GRID, 256>>>(inp, W, bias, alpha, beta, out);
}

// round 13
// speedup vs baseline: 1.0005x; 1.0005x over previous
#include <cuda_runtime.h>
#include <cstdint>

// Problem constants
#define BSZ     256
#define IDIM    182
#define TSTEPS  2000
#define H0LEN   1024         // half 0: t in [0,1024)    -- 128B-aligned rows
#define H1LEN   976          // half 1: t in [1024,2000) -- base offset 4096B, aligned
#define OCH     2
#define CHUNK   4            // steps per thread in scan phase
#define GRID    (BSZ * 2)    // CTA 2b+h: batch b, t-half h

// TMA pipeline shape
#define RPG       4                       // input rows per pipeline group
#define NST       3                       // pipeline stages
#define NG        ((IDIM + RPG - 1) / RPG)  // 46 groups (last has 2 rows)
#define ROWPITCH  4096                    // staged row pitch (bytes)
#define STAGEB    (RPG * ROWPITCH)        // 16384 B per stage

// dynamic SMEM layout (bytes)
#define SM_SBUF   0
#define SM_W      (NST * STAGEB)          // 49152
#define SM_MBAR   (SM_W + 1472)           // W = 2*182*4 = 1456, pad to 1472
#define SM_TS     (SM_MBAR + 32)          // 3 mbarriers (24 B), pad to 32
#define SM_ES     (SM_TS + 128)
#define SM_BND    (SM_ES + 128)
#define SM_TOTAL  (SM_BND + 16)           // 50928

// boundary handoff: half-0 final state (syn0,mem0,syn1,mem1) + flag per batch
__device__ float g_state[BSZ][4];
__device__ volatile unsigned g_flag[BSZ];   // zero-init; consumer resets -> replay-safe

// ---- PTX helpers -----------------------------------------------------------
__device__ __forceinline__ uint32_t smem_u32(const void* p) {
    uint32_t a;
    asm("{ .reg .u64 t; cvta.to.shared.u64 t, %1; cvt.u32.u64 %0, t; }"
        : "=r"(a) : "l"(p));
    return a;
}
__device__ __forceinline__ void mbar_init(uint32_t mb, uint32_t cnt) {
    asm volatile("mbarrier.init.shared.b64 [%0], %1;" :: "r"(mb), "r"(cnt) : "memory");
}
__device__ __forceinline__ void mbar_expect_tx(uint32_t mb, uint32_t bytes) {
    asm volatile("mbarrier.arrive.expect_tx.shared.b64 _, [%0], %1;"
                 :: "r"(mb), "r"(bytes) : "memory");
}
__device__ __forceinline__ void mbar_wait(uint32_t mb, uint32_t ph) {
    asm volatile(
        "{\n\t.reg .pred P;\n\t"
        "WL_%=:\n\t"
        "mbarrier.try_wait.parity.acquire.cta.shared::cta.b64 P, [%0], %1, 0x989680;\n\t"
        "@P bra.uni WD_%=;\n\t"
        "bra.uni WL_%=;\n\t"
        "WD_%=:\n\t}"
        :: "r"(mb), "r"(ph) : "memory");
}
__device__ __forceinline__ void bulk_g2s(uint32_t dst, const void* src,
                                         uint32_t bytes, uint32_t mb) {
    asm volatile(
        "cp.async.bulk.shared::cluster.global.mbarrier::complete_tx::bytes "
        "[%0], [%1], %2, [%3];"
        :: "r"(dst), "l"(src), "r"(bytes), "r"(mb) : "memory");
}

// ---------------------------------------------------------------------------
// Fully fused kernel, TMA-pipelined GEMM + register-resident chunked scan.
//   Phase 1: 3-stage cp.async.bulk pipeline stages 4 input rows (<=16KB) at a
//   time into SMEM; 256 threads FMA from SMEM into per-thread float4 currents.
//   Phase 2: log-depth scan of syn_t = a*syn+c ; mem_t = m*mem+syn directly on
//   the register-resident currents (thread j's scan chunk IS its accumulator).
//   Half 1 seeds its composition with half 0's boundary state (affine scan).
//   Spin safety: __launch_bounds__(256,4) + 51KB smem -> 4 CTAs/SM -> all 512
//   CTAs co-resident (592 slots); producer never blocks.
// ---------------------------------------------------------------------------
__global__ __launch_bounds__(256, 4)
void snn_fused_kernel(const float* __restrict__ inp,   // [B, I, T]
                      const float* __restrict__ W,     // [O, I]
                      const float* __restrict__ bias,  // [O]
                      const float* __restrict__ alpha,
                      const float* __restrict__ beta,
                      float* __restrict__ out)         // [B, T, O]
{
    extern __shared__ char smem[];
    float* Wsh = (float*)(smem + SM_W);     // [2*182] flat: o*IDIM + i
    float* ts  = (float*)(smem + SM_TS);    // [o][w][2] -> o*16 + w*2 + k
    float* es  = (float*)(smem + SM_ES);
    float* bnd = (float*)(smem + SM_BND);

    const uint32_t smb   = smem_u32(smem);
    const uint32_t sbuf0 = smb + SM_SBUF;
    const uint32_t mbar0 = smb + SM_MBAR;

    const int tid = threadIdx.x;
    const int b   = blockIdx.x >> 1;
    const int h   = blockIdx.x & 1;

    const int tbase = h ? H0LEN : 0;
    const int nch   = h ? (H1LEN / 4) : (H0LEN / 4);   // 244 or 256 live threads
    const bool gl   = (tid < nch);
    const uint32_t rowbytes = (h ? H1LEN : H0LEN) * 4; // 3904 / 4096 (both %16==0)

    const float* rowsrc = inp + (size_t)b * IDIM * TSTEPS + tbase;

    // ---- pipeline init + prologue issue (before W load: stream starts now) --
    if (tid == 0) {
        mbar_init(mbar0 + 0,  1);
        mbar_init(mbar0 + 8,  1);
        mbar_init(mbar0 + 16, 1);
    }
    __syncthreads();
    asm volatile("fence.proxy.async.shared::cta;" ::: "memory");
    if (tid == 0) {
        #pragma unroll
        for (int g = 0; g < NST; g++) {
            const int i0 = g * RPG;
            const int rows = (i0 + RPG <= IDIM) ? RPG : (IDIM - i0);
            const uint32_t mb = mbar0 + g * 8;
            mbar_expect_tx(mb, (uint32_t)rows * rowbytes);
            for (int r = 0; r < rows; r++)
                bulk_g2s(sbuf0 + g * STAGEB + r * ROWPITCH,
                         rowsrc + (size_t)(i0 + r) * TSTEPS, rowbytes, mb);
        }
    }
    for (int k = tid; k < OCH * IDIM; k += 256)
        Wsh[k] = W[k];
    __syncthreads();

    // ======================= phase 1: pipelined GEMM =========================
    float4 acc0 = make_float4(0.f, 0.f, 0.f, 0.f);
    float4 acc1 = make_float4(0.f, 0.f, 0.f, 0.f);

    for (int g = 0; g < NG; g++) {
        const int slot   = g % NST;
        const uint32_t ph = (uint32_t)((g / NST) & 1);
        mbar_wait(mbar0 + slot * 8, ph);

        if (gl) {
            const int i0 = g * RPG;
            const char* base = smem + SM_SBUF + slot * STAGEB + tid * 16;
            #pragma unroll
            for (int r = 0; r < RPG; r++) {
                if (i0 + r < IDIM) {
                    const float4 x = *reinterpret_cast<const float4*>(base + r * ROWPITCH);
                    const float w0 = Wsh[i0 + r];
                    const float w1 = Wsh[IDIM + i0 + r];
                    acc0.x = fmaf(w0, x.x, acc0.x); acc0.y = fmaf(w0, x.y, acc0.y);
                    acc0.z = fmaf(w0, x.z, acc0.z); acc0.w = fmaf(w0, x.w, acc0.w);
                    acc1.x = fmaf(w1, x.x, acc1.x); acc1.y = fmaf(w1, x.y, acc1.y);
                    acc1.z = fmaf(w1, x.z, acc1.z); acc1.w = fmaf(w1, x.w, acc1.w);
                }
            }
        }
        __syncthreads();   // all threads done reading this stage

        const int ng2 = g + NST;
        if (tid == 0 && ng2 < NG) {
            const int i0 = ng2 * RPG;
            const int rows = (i0 + RPG <= IDIM) ? RPG : (IDIM - i0);
            const uint32_t mb = mbar0 + slot * 8;
            mbar_expect_tx(mb, (uint32_t)rows * rowbytes);
            for (int r = 0; r < rows; r++)
                bulk_g2s(sbuf0 + slot * STAGEB + r * ROWPITCH,
                         rowsrc + (size_t)(i0 + r) * TSTEPS, rowbytes, mb);
        }
    }

    if (gl) {
        const float b0 = bias[0], b1 = bias[1];
        acc0.x += b0; acc0.y += b0; acc0.z += b0; acc0.w += b0;
        acc1.x += b1; acc1.y += b1; acc1.z += b1; acc1.w += b1;
    }

    // ======================= phase 2: scan (register currents) ==============
    const int j    = tid;
    const int lane = j & 31;
    const int w    = j >> 5;

    float a[OCH], m[OCH];
    a[0] = __saturatef(alpha[0]); a[1] = __saturatef(alpha[1]);
    m[0] = __saturatef(beta[0]);  m[1] = __saturatef(beta[1]);

    float c[OCH][CHUNK];
    c[0][0] = acc0.x; c[0][1] = acc0.y; c[0][2] = acc0.z; c[0][3] = acc0.w;
    c[1][0] = acc1.x; c[1][1] = acc1.y; c[1][2] = acc1.z; c[1][3] = acc1.w;

    float vs[OCH], vm[OCH];
    #pragma unroll
    for (int o = 0; o < OCH; o++) {
        float s = 0.f, q = 0.f;
        #pragma unroll
        for (int k = 0; k < CHUNK; k++) {
            s = fmaf(a[o], s, c[o][k]);
            q = fmaf(m[o], q, s);
        }
        vs[o] = s; vm[o] = q;
    }

    // P = M^CHUNK per channel:  M = [[a,0],[a,m]], M^k = [[A,0],[C,B]]
    float PA[OCH], PB[OCH], PC[OCH];
    #pragma unroll
    for (int o = 0; o < OCH; o++) {
        float A = 1.f, B = 1.f, C = 0.f;
        #pragma unroll
        for (int k = 0; k < CHUNK; k++) {
            A = a[o] * A;
            C = fmaf(m[o], C, A);
            B = m[o] * B;
        }
        PA[o] = A; PB[o] = B; PC[o] = C;
    }

    // Kogge-Stone intra-warp scan; build L = P^lane on the fly
    float LA[OCH] = {1.f, 1.f}, LB[OCH] = {1.f, 1.f}, LC[OCH] = {0.f, 0.f};
    #pragma unroll
    for (int d = 1; d <= 16; d <<= 1) {
        #pragma unroll
        for (int o = 0; o < OCH; o++) {
            if (lane & d) {
                const float nA = LA[o] * PA[o];
                const float nB = LB[o] * PB[o];
                const float nC = fmaf(LC[o], PA[o], LB[o] * PC[o]);
                LA[o] = nA; LB[o] = nB; LC[o] = nC;
            }
        }
        #pragma unroll
        for (int o = 0; o < OCH; o++) {
            const float ws = __shfl_up_sync(0xffffffffu, vs[o], d);
            const float wq = __shfl_up_sync(0xffffffffu, vm[o], d);
            if (lane >= d) {
                vm[o] = fmaf(PC[o], ws, fmaf(PB[o], wq, vm[o]));
                vs[o] = fmaf(PA[o], ws, vs[o]);
            }
        }
        #pragma unroll
        for (int o = 0; o < OCH; o++) {
            PC[o] = PC[o] * (PA[o] + PB[o]);
            PA[o] = PA[o] * PA[o];
            PB[o] = PB[o] * PB[o];
        }
    }
    // P now holds P^32 (warp-span matrix)

    if (lane == 31) {
        #pragma unroll
        for (int o = 0; o < OCH; o++) {
            ts[o * 16 + w * 2 + 0] = vs[o];
            ts[o * 16 + w * 2 + 1] = vm[o];
        }
    }

    // boundary seed: half 0 -> zeros; half 1 -> wait for half 0's final state
    if (tid == 0) {
        if (h == 1) {
            while (g_flag[b] == 0u) { /* brief spin; producer co-resident */ }
            __threadfence();            // acquire
            bnd[0] = g_state[b][0];
            bnd[1] = g_state[b][1];
            bnd[2] = g_state[b][2];
            bnd[3] = g_state[b][3];
            g_flag[b] = 0u;             // reset for next graph replay
        } else {
            bnd[0] = 0.f; bnd[1] = 0.f; bnd[2] = 0.f; bnd[3] = 0.f;
        }
    }
    __syncthreads();

    // serial composition over 8 warp totals, seeded with boundary state.
    // h=0: the final (Ss,Sm) is exactly the state after t=1023 -> publish now.
    if (j < OCH) {
        const int o = j;
        float Ss = bnd[2 * o + 0];
        float Sm = bnd[2 * o + 1];
        #pragma unroll
        for (int k = 0; k < 8; k++) {
            es[o * 16 + k * 2 + 0] = Ss;
            es[o * 16 + k * 2 + 1] = Sm;
            const float tsv = ts[o * 16 + k * 2 + 0];
            const float tmv = ts[o * 16 + k * 2 + 1];
            const float ns = fmaf(PA[o], Ss, tsv);
            const float nm = fmaf(PC[o], Ss, fmaf(PB[o], Sm, tmv));
            Ss = ns; Sm = nm;
        }
        if (h == 0) {
            g_state[b][2 * o + 0] = Ss;
            g_state[b][2 * o + 1] = Sm;
            __threadfence();            // release state pair
        }
    }
    __syncthreads();
    if (h == 0 && tid == 0) {
        __threadfence();
        g_flag[b] = 1u;                 // release flag after both pairs
    }

    // replay with true prefix state; streaming float4 stores
    if (gl) {
        float pre_s[OCH], pre_m[OCH];
        #pragma unroll
        for (int o = 0; o < OCH; o++) {
            float Xs = __shfl_up_sync(0xffffffffu, vs[o], 1);
            float Xm = __shfl_up_sync(0xffffffffu, vm[o], 1);
            if (lane == 0) { Xs = 0.f; Xm = 0.f; }
            const float esv = es[o * 16 + w * 2 + 0];
            const float emv = es[o * 16 + w * 2 + 1];
            pre_s[o] = fmaf(LA[o], esv, Xs);
            pre_m[o] = fmaf(LC[o], esv, fmaf(LB[o], emv, Xm));
        }
        float s0 = pre_s[0], q0 = pre_m[0];
        float s1 = pre_s[1], q1 = pre_m[1];

        float r[2 * CHUNK];
        #pragma unroll
        for (int k = 0; k < CHUNK; k++) {
            s0 = fmaf(a[0], s0, c[0][k]); q0 = fmaf(m[0], q0, s0);
            s1 = fmaf(a[1], s1, c[1][k]); q1 = fmaf(m[1], q1, s1);
            r[2 * k + 0] = q0;
            r[2 * k + 1] = q1;
        }

        float4* ob = reinterpret_cast<float4*>(out + ((size_t)b * TSTEPS + tbase + j * 4) * OCH);
        __stcs(ob + 0, make_float4(r[0], r[1], r[2], r[3]));
        __stcs(ob + 1, make_float4(r[4], r[5], r[6], r[7]));
    }
}

extern "C" void kernel_launch(void* const* d_in, const int* in_sizes, int n_in,
                              void* d_out, int out_size)
{
    const float* inp   = (const float*)d_in[0]; // [256,182,2000]
    const float* W     = (const float*)d_in[1]; // [2,182]
    const float* bias  = (const float*)d_in[2]; // [2]
    const float* alpha = (const float*)d_in[3]; // [2]
    const float* beta  = (const float*)d_in[4]; // [2]
    float* out = (float*)d_out;                 // [256,2000,2]

    cudaFuncSetAttribute(snn_fused_kernel,
                         cudaFuncAttributeMaxDynamicSharedMemorySize, SM_TOTAL);
    snn_fused_kernel<<<GRID, 256, SM_TOTAL>>>(inp, W, bias, alpha, beta, out);
}